// round 13
// baseline (speedup 1.0000x reference)
#include <cuda_runtime.h>
#include <cuda_fp16.h>
#include <cstdint>

// LuongAttention: O[b] = (Q Eᵀ) E == Q (EᵀE).  G = EᵀE per batch (128x128).
// fp16 split 2-term products: x·y ≈ hi_x·(hi_y + lo_y) (err ~2e-4).
// R13: single fused kernel (256 CTAs x 256 thr, all co-resident at occ 2)
// with a monotonic-counter grid barrier.  Phase 1 = ete split-k, phase 2 =
// reduce -> G fragments, phase 3 = qg.  Each CTA loads + splits its qg Q-tile
// into smem DURING phase 1's MMAs, so phase 3 starts with zero DRAM prologue.

#define BB 8
#define NSPLIT 16
#define NCTA 256
#define RSTRIDE 272                 // plane row stride, bytes
#define PLANE_T (64 * RSTRIDE)      // 17408 B
#define STAGE_SZ (2 * PLANE_T)      // hi + lo planes per stage
#define QOFF (2 * STAGE_SZ)         // Q plane offset in smem
#define SMEM_SZ (QOFF + PLANE_T)    // 87040 B

__device__ float g_part[BB * NSPLIT * 128 * 128];   // 8 MB partials
// B-fragment layout: [b][n8tile 16][kstep 8][lane 32] = uint4
//   uint4 = { hi_b0, hi_b1, lo_b0, lo_b1 } (fp16x2 each).
__device__ uint4 g_frag[BB * 16 * 8 * 32];          // 512 KB
__device__ unsigned g_bar[2] = {0u, 0u};            // monotonic barrier ctrs

// ---------------- helpers ----------------
__device__ __forceinline__ uint32_t smem_u32(const void* p) {
    uint32_t a;
    asm("{ .reg .u64 t; cvta.to.shared.u64 t, %1; cvt.u32.u64 %0, t; }"
        : "=r"(a) : "l"(p));
    return a;
}
__device__ __forceinline__ void ldsm_x4(uint32_t (&r)[4], uint32_t addr) {
    asm volatile("ldmatrix.sync.aligned.m8n8.x4.shared.b16 {%0,%1,%2,%3}, [%4];"
                 : "=r"(r[0]), "=r"(r[1]), "=r"(r[2]), "=r"(r[3]) : "r"(addr));
}
__device__ __forceinline__ void ldsm_x4_t(uint32_t (&r)[4], uint32_t addr) {
    asm volatile("ldmatrix.sync.aligned.m8n8.x4.trans.shared.b16 {%0,%1,%2,%3}, [%4];"
                 : "=r"(r[0]), "=r"(r[1]), "=r"(r[2]), "=r"(r[3]) : "r"(addr));
}
__device__ __forceinline__ void mma16816(float (&d)[4], const uint32_t (&a)[4],
                                         uint32_t b0, uint32_t b1) {
    asm volatile(
        "mma.sync.aligned.m16n8k16.row.col.f32.f16.f16.f32 "
        "{%0,%1,%2,%3}, {%4,%5,%6,%7}, {%8,%9}, {%0,%1,%2,%3};"
        : "+f"(d[0]), "+f"(d[1]), "+f"(d[2]), "+f"(d[3])
        : "r"(a[0]), "r"(a[1]), "r"(a[2]), "r"(a[3]), "r"(b0), "r"(b1));
}
__device__ __forceinline__ void split2h(float f0, float f1, uint32_t& hi, uint32_t& lo) {
    __half2 h = __floats2half2_rn(f0, f1);
    float2 hf = __half22float2(h);
    __half2 l = __floats2half2_rn(f0 - hf.x, f1 - hf.y);
    hi = *(uint32_t*)&h;
    lo = *(uint32_t*)&l;
}
__device__ __forceinline__ uint32_t pack2h(float f0, float f1) {
    __half2 h = __floats2half2_rn(f0, f1);
    return *(uint32_t*)&h;
}

// Grid barrier: monotonic counter, NCTA a power of two -> (cnt & (NCTA-1))==0
// exactly when all CTAs of this launch have arrived.  Never reset; safe
// across graph replays (launches are stream-serialized).
__device__ __forceinline__ void grid_bar(int slot) {
    __syncthreads();
    if (threadIdx.x == 0) {
        __threadfence();
        atomicAdd(&g_bar[slot], 1u);
        while (atomicAdd(&g_bar[slot], 0u) & (NCTA - 1)) __nanosleep(64);
        __threadfence();
    }
    __syncthreads();
}

// Split+store one 64-token register batch into a stage's hi/lo planes.
__device__ __forceinline__ void stage_store(char* smem, int stage, int tid,
                                            const float4* q) {
    char* base = smem + stage * STAGE_SZ;
#pragma unroll
    for (int v = 0; v < 8; v++) {
        int idx = tid + v * 256;
        int t = idx >> 5, d4 = idx & 31;
        uint32_t h0, l0, h1, l1;
        split2h(q[v].x, q[v].y, h0, l0);
        split2h(q[v].z, q[v].w, h1, l1);
        uint32_t off = (uint32_t)t * RSTRIDE + (uint32_t)d4 * 8;
        *(uint2*)(base + off) = make_uint2(h0, h1);
        *(uint2*)(base + PLANE_T + off) = make_uint2(l0, l1);
    }
}

// MMA over one 64-token stage (4 ksteps), trans layout, 32x32 warp tile.
__device__ __forceinline__ void stage_mma(uint32_t sbase, int wm, int wn, int lid,
                                          float (&acc)[2][4][4]) {
    const uint32_t aRow = (lid & 7) + ((lid >> 4) << 3);
    const uint32_t aCol = ((lid >> 3) & 1) << 3;
    const uint32_t bRow = (lid & 7) + (((lid >> 3) & 1) << 3);
    const uint32_t bCol = (lid >> 4) << 3;

#pragma unroll
    for (int kk = 0; kk < 4; kk++) {
        const int k0 = kk * 16;
        uint32_t Ah[2][4], Bh[2][4], Bl[2][4];
#pragma unroll
        for (int mi = 0; mi < 2; mi++) {
            uint32_t off = (uint32_t)(k0 + aRow) * RSTRIDE +
                           (uint32_t)(wm + mi * 16 + aCol) * 2;
            ldsm_x4_t(Ah[mi], sbase + off);
        }
#pragma unroll
        for (int np = 0; np < 2; np++) {
            uint32_t off = (uint32_t)(k0 + bRow) * RSTRIDE +
                           (uint32_t)(wn + np * 16 + bCol) * 2;
            ldsm_x4_t(Bh[np], sbase + off);
            ldsm_x4_t(Bl[np], sbase + PLANE_T + off);
        }
#pragma unroll
        for (int mi = 0; mi < 2; mi++)
#pragma unroll
            for (int nj = 0; nj < 4; nj++) {
                const int np = nj >> 1, pr = (nj & 1) << 1;
                mma16816(acc[mi][nj], Ah[mi], Bh[np][pr], Bh[np][pr + 1]);
            }
#pragma unroll
        for (int mi = 0; mi < 2; mi++)
#pragma unroll
            for (int nj = 0; nj < 4; nj++) {
                const int np = nj >> 1, pr = (nj & 1) << 1;
                mma16816(acc[mi][nj], Ah[mi], Bl[np][pr], Bl[np][pr + 1]);
            }
    }
}

// ---------------------------------------------------------------------------
// Fused kernel: 256 CTAs x 256 threads, occ 2 (all co-resident).
// ---------------------------------------------------------------------------
__global__ __launch_bounds__(256, 2) void fused(const float* __restrict__ enc,
                                                const float* __restrict__ dec,
                                                float* __restrict__ out) {
    extern __shared__ char smem[];
    const uint32_t sb = smem_u32(smem);
    const int tid = threadIdx.x, wid = tid >> 5, lid = tid & 31;
    const int cid = blockIdx.x;

    // ================= Phase 1: ete (R9 structure) =================
    {
        const int eb = cid >> 5, ebx = cid & 31, sp = ebx >> 1, half = ebx & 1;
        const float4* src =
            (const float4*)(enc + (size_t)(eb * NSPLIT + sp) * (128 * 128));

        float4 q[8];
#pragma unroll
        for (int v = 0; v < 8; v++) q[v] = src[tid + v * 256];
        stage_store(smem, 0, tid, q);
        __syncthreads();

        // Stage-1 loads fly under stage-0 MMA.
#pragma unroll
        for (int v = 0; v < 8; v++) q[v] = src[2048 + tid + v * 256];

        const int wm = half * 64 + (wid >> 2) * 32, wn = (wid & 3) * 32;
        float acc[2][4][4];
#pragma unroll
        for (int mi = 0; mi < 2; mi++)
#pragma unroll
            for (int nj = 0; nj < 4; nj++)
#pragma unroll
                for (int r = 0; r < 4; r++) acc[mi][nj][r] = 0.0f;

        stage_mma(sb, wm, wn, lid, acc);            // tokens 0..63

        stage_store(smem, 1, tid, q);
        __syncthreads();

        // qg Q-tile loads fly under stage-1 MMA (Q doesn't depend on G).
        const float4* qsrc = (const float4*)(dec + ((size_t)cid << 13));
        float4 qq[8];
#pragma unroll
        for (int v = 0; v < 8; v++) qq[v] = qsrc[tid + v * 256];

        stage_mma(sb + STAGE_SZ, wm, wn, lid, acc); // tokens 64..127

        // Park Q hi-plane in smem across the barriers.
#pragma unroll
        for (int v = 0; v < 8; v++) {
            int idx = tid + v * 256;
            int row = idx >> 5, d4 = idx & 31;
            uint32_t off = (uint32_t)row * RSTRIDE + (uint32_t)d4 * 8;
            *(uint2*)(smem + QOFF + off) =
                make_uint2(pack2h(qq[v].x, qq[v].y), pack2h(qq[v].z, qq[v].w));
        }

        // Epilogue: write partial tile.
        float* outp = g_part + ((size_t)(eb * NSPLIT + sp) << 14);
        const int g = lid >> 2, tig = lid & 3;
#pragma unroll
        for (int mi = 0; mi < 2; mi++)
#pragma unroll
            for (int nj = 0; nj < 4; nj++) {
                const int row = wm + mi * 16 + g;
                const int col = wn + nj * 8 + 2 * tig;
                *(float2*)(outp + row * 128 + col) =
                    make_float2(acc[mi][nj][0], acc[mi][nj][1]);
                *(float2*)(outp + (row + 8) * 128 + col) =
                    make_float2(acc[mi][nj][2], acc[mi][nj][3]);
            }
    }

    grid_bar(0);

    // ================= Phase 2: reduce -> G fragments =================
    {
        const int e2 = cid * 256 + tid;          // 0..65535
        const int rb = e2 >> 13;
        const int r = e2 & 8191;
        const int j = r >> 6, d2 = r & 63;
        const float2* base =
            (const float2*)(g_part + ((size_t)rb << 18) + j * 128) + d2;
        float sx = 0.f, sy = 0.f;
#pragma unroll
        for (int sp = 0; sp < NSPLIT; sp++) {
            float2 v = __ldcg(base + ((size_t)sp << 13));  // L2 (cross-SM)
            sx += v.x; sy += v.y;
        }
        uint32_t hi, lo;
        split2h(sx, sy, hi, lo);
        const uint32_t lane = (uint32_t)(j & 7) * 4 + (d2 & 3);
        const uint32_t comp = (uint32_t)(d2 >> 2) & 1;
        const uint32_t slot =
            (((uint32_t)(rb * 16 + (j >> 3)) * 8 + (d2 >> 3)) * 32 + lane);
        uint32_t* f = (uint32_t*)g_frag + slot * 4;
        f[comp] = hi;
        f[comp + 2] = lo;
    }

    grid_bar(1);

    // ================= Phase 3: qg (R9 structure; Q already in smem) =======
    {
        const int b = cid >> 5;
        const int wm = (wid >> 2) * 32, wn = (wid & 3) * 32;
        const uint4* gf = g_frag + ((size_t)(b * 16 + (wn >> 3)) * 8) * 32 + lid;

        float acc[2][4][4];
#pragma unroll
        for (int mi = 0; mi < 2; mi++)
#pragma unroll
            for (int nj = 0; nj < 4; nj++)
#pragma unroll
                for (int r = 0; r < 4; r++) acc[mi][nj][r] = 0.0f;

        const uint32_t aRow = lid & 15;
        const uint32_t aCol = (lid >> 4) << 3;
        const uint32_t qpl = sb + QOFF;

        uint4 Gb[2][4];
#pragma unroll
        for (int nj = 0; nj < 4; nj++) Gb[0][nj] = __ldcg(gf + nj * 256);
#pragma unroll
        for (int nj = 0; nj < 4; nj++) Gb[1][nj] = __ldcg(gf + nj * 256 + 32);

#pragma unroll
        for (int kk = 0; kk < 8; kk++) {
            const int k0 = kk * 16;
            const int buf = kk & 1;
            uint32_t Ah[2][4];
#pragma unroll
            for (int mi = 0; mi < 2; mi++) {
                uint32_t off = (uint32_t)(wm + mi * 16 + aRow) * RSTRIDE +
                               (uint32_t)(k0 + aCol) * 2;
                ldsm_x4(Ah[mi], qpl + off);
            }
#pragma unroll
            for (int mi = 0; mi < 2; mi++)
#pragma unroll
                for (int nj = 0; nj < 4; nj++)
                    mma16816(acc[mi][nj], Ah[mi], Gb[buf][nj].x, Gb[buf][nj].y);
#pragma unroll
            for (int mi = 0; mi < 2; mi++)
#pragma unroll
                for (int nj = 0; nj < 4; nj++)
                    mma16816(acc[mi][nj], Ah[mi], Gb[buf][nj].z, Gb[buf][nj].w);
            if (kk < 6) {
#pragma unroll
                for (int nj = 0; nj < 4; nj++)
                    Gb[buf][nj] = __ldcg(gf + nj * 256 + (kk + 2) * 32);
            }
        }

        float* outp = out + ((size_t)cid << 13);
        const int g = lid >> 2, tig = lid & 3;
#pragma unroll
        for (int mi = 0; mi < 2; mi++)
#pragma unroll
            for (int nj = 0; nj < 4; nj++) {
                const int row = wm + mi * 16 + g;
                const int col = wn + nj * 8 + 2 * tig;
                *(float2*)(outp + row * 128 + col) =
                    make_float2(acc[mi][nj][0], acc[mi][nj][1]);
                *(float2*)(outp + (row + 8) * 128 + col) =
                    make_float2(acc[mi][nj][2], acc[mi][nj][3]);
            }
    }
}

// ---------------------------------------------------------------------------
// Launch
// ---------------------------------------------------------------------------
extern "C" void kernel_launch(void* const* d_in, const int* in_sizes, int n_in,
                              void* d_out, int out_size) {
    const float* enc = (const float*)d_in[0];
    const float* dec = (const float*)d_in[1];
    float* out = (float*)d_out;

    cudaFuncSetAttribute(fused, cudaFuncAttributeMaxDynamicSharedMemorySize,
                         SMEM_SZ);
    fused<<<NCTA, 256, SMEM_SZ>>>(enc, dec, out);
}

// round 14
// speedup vs baseline: 1.1765x; 1.1765x over previous
#include <cuda_runtime.h>
#include <cuda_fp16.h>
#include <cstdint>

// LuongAttention: O[b] = (Q Eᵀ) E == Q (EᵀE).  G = EᵀE per batch (128x128).
// R14: single-term fp16 (hi planes only) in BOTH GEMMs — spend the unused
// error budget (model: ~4e-4 vs 1e-3 tolerance).  Halves MMAs, LDSM, split
// math, STS and smem vs R9.  Structure = R9 (best measured skeleton):
// ete split-k double-buffered, reduce->fragments, qg with gmem fragments.

#define BB 8
#define NSPLIT 16
#define RSTRIDE 272                 // plane row stride, bytes
#define PLANE_T (64 * RSTRIDE)      // 17408 B (hi plane, 64 tokens)
#define STAGE_SZ PLANE_T            // one (hi-only) plane per stage

__device__ float g_part[BB * NSPLIT * 128 * 128];   // 8 MB partials
// B-fragment layout: [b][n8tile 16][kstep 8][lane 32] = uint2 {hi_b0, hi_b1}.
__device__ uint2 g_frag[BB * 16 * 8 * 32];          // 256 KB

// ---------------- helpers ----------------
__device__ __forceinline__ uint32_t smem_u32(const void* p) {
    uint32_t a;
    asm("{ .reg .u64 t; cvta.to.shared.u64 t, %1; cvt.u32.u64 %0, t; }"
        : "=r"(a) : "l"(p));
    return a;
}
__device__ __forceinline__ void ldsm_x4(uint32_t (&r)[4], uint32_t addr) {
    asm volatile("ldmatrix.sync.aligned.m8n8.x4.shared.b16 {%0,%1,%2,%3}, [%4];"
                 : "=r"(r[0]), "=r"(r[1]), "=r"(r[2]), "=r"(r[3]) : "r"(addr));
}
__device__ __forceinline__ void ldsm_x4_t(uint32_t (&r)[4], uint32_t addr) {
    asm volatile("ldmatrix.sync.aligned.m8n8.x4.trans.shared.b16 {%0,%1,%2,%3}, [%4];"
                 : "=r"(r[0]), "=r"(r[1]), "=r"(r[2]), "=r"(r[3]) : "r"(addr));
}
__device__ __forceinline__ void mma16816(float (&d)[4], const uint32_t (&a)[4],
                                         uint32_t b0, uint32_t b1) {
    asm volatile(
        "mma.sync.aligned.m16n8k16.row.col.f32.f16.f16.f32 "
        "{%0,%1,%2,%3}, {%4,%5,%6,%7}, {%8,%9}, {%0,%1,%2,%3};"
        : "+f"(d[0]), "+f"(d[1]), "+f"(d[2]), "+f"(d[3])
        : "r"(a[0]), "r"(a[1]), "r"(a[2]), "r"(a[3]), "r"(b0), "r"(b1));
}
__device__ __forceinline__ uint32_t pack2h(float f0, float f1) {
    __half2 h = __floats2half2_rn(f0, f1);
    return *(uint32_t*)&h;
}

__device__ __forceinline__ void warp_epilogue32(float* outp, int wm, int wn, int lid,
                                                float (&acc)[2][4][4]) {
    const int g = lid >> 2, tig = lid & 3;
#pragma unroll
    for (int mi = 0; mi < 2; mi++)
#pragma unroll
        for (int nj = 0; nj < 4; nj++) {
            const int row = wm + mi * 16 + g;
            const int col = wn + nj * 8 + 2 * tig;
            *(float2*)(outp + row * 128 + col) =
                make_float2(acc[mi][nj][0], acc[mi][nj][1]);
            *(float2*)(outp + (row + 8) * 128 + col) =
                make_float2(acc[mi][nj][2], acc[mi][nj][3]);
        }
}

// Convert+store one 64-token register batch into a stage's hi plane.
__device__ __forceinline__ void stage_store(char* smem, int stage, int tid,
                                            const float4* q) {
    char* base = smem + stage * STAGE_SZ;
#pragma unroll
    for (int v = 0; v < 8; v++) {
        int idx = tid + v * 256;
        int t = idx >> 5, d4 = idx & 31;
        uint32_t off = (uint32_t)t * RSTRIDE + (uint32_t)d4 * 8;
        *(uint2*)(base + off) =
            make_uint2(pack2h(q[v].x, q[v].y), pack2h(q[v].z, q[v].w));
    }
}

// MMA over one 64-token stage (4 ksteps), trans layout, 32x32 warp tile,
// single term (hi·hi).
__device__ __forceinline__ void stage_mma(uint32_t sbase, int wm, int wn, int lid,
                                          float (&acc)[2][4][4]) {
    const uint32_t aRow = (lid & 7) + ((lid >> 4) << 3);
    const uint32_t aCol = ((lid >> 3) & 1) << 3;
    const uint32_t bRow = (lid & 7) + (((lid >> 3) & 1) << 3);
    const uint32_t bCol = (lid >> 4) << 3;

#pragma unroll
    for (int kk = 0; kk < 4; kk++) {
        const int k0 = kk * 16;
        uint32_t Ah[2][4], Bh[2][4];
#pragma unroll
        for (int mi = 0; mi < 2; mi++) {
            uint32_t off = (uint32_t)(k0 + aRow) * RSTRIDE +
                           (uint32_t)(wm + mi * 16 + aCol) * 2;
            ldsm_x4_t(Ah[mi], sbase + off);
        }
#pragma unroll
        for (int np = 0; np < 2; np++) {
            uint32_t off = (uint32_t)(k0 + bRow) * RSTRIDE +
                           (uint32_t)(wn + np * 16 + bCol) * 2;
            ldsm_x4_t(Bh[np], sbase + off);
        }
#pragma unroll
        for (int mi = 0; mi < 2; mi++)
#pragma unroll
            for (int nj = 0; nj < 4; nj++) {
                const int np = nj >> 1, pr = (nj & 1) << 1;
                mma16816(acc[mi][nj], Ah[mi], Bh[np][pr], Bh[np][pr + 1]);
            }
    }
}

// ---------------------------------------------------------------------------
// Kernel 1: partial EᵀE.  CTA (sp, half): K = 128 tokens in two 64-token
// stages, double-buffered; stage-1 LDG overlaps stage-0 MMA.
// Grid (2*NSPLIT, BB); bx = sp*2 + half.
// ---------------------------------------------------------------------------
__global__ __launch_bounds__(256) void ete_hmma(const float* __restrict__ enc) {
    extern __shared__ char smem[];
    const uint32_t sb = smem_u32(smem);
    const int tid = threadIdx.x, wid = tid >> 5, lid = tid & 31;
    const int sp = blockIdx.x >> 1, half = blockIdx.x & 1, b = blockIdx.y;

    const float4* src =
        (const float4*)(enc + (size_t)(b * NSPLIT + sp) * (128 * 128));

    float4 q0[8];
#pragma unroll
    for (int v = 0; v < 8; v++) q0[v] = src[tid + v * 256];
    stage_store(smem, 0, tid, q0);
    __syncthreads();

    // Stage 1 loads issued NOW — they fly while stage-0 MMAs run.
    float4 q1[8];
#pragma unroll
    for (int v = 0; v < 8; v++) q1[v] = src[2048 + tid + v * 256];

    const int wm = half * 64 + (wid >> 2) * 32, wn = (wid & 3) * 32;
    float acc[2][4][4];
#pragma unroll
    for (int mi = 0; mi < 2; mi++)
#pragma unroll
        for (int nj = 0; nj < 4; nj++)
#pragma unroll
            for (int r = 0; r < 4; r++) acc[mi][nj][r] = 0.0f;

    stage_mma(sb, wm, wn, lid, acc);            // tokens 0..63

    stage_store(smem, 1, tid, q1);
    __syncthreads();

    stage_mma(sb + STAGE_SZ, wm, wn, lid, acc); // tokens 64..127

    warp_epilogue32(g_part + ((size_t)(b * NSPLIT + sp) << 14), wm, wn, lid, acc);
}

// ---------------------------------------------------------------------------
// Kernel 2: reduce 16 partials; emit G rows as fp16 hi-only B-fragments.
// ---------------------------------------------------------------------------
__global__ __launch_bounds__(256) void reduce_g() {
    const int e2 = blockIdx.x * 256 + threadIdx.x;  // 0..65535
    const int b = e2 >> 13;
    const int r = e2 & 8191;
    const int j = r >> 6, d2 = r & 63;
    const float2* base =
        (const float2*)(g_part + ((size_t)b << 18) + j * 128) + d2;
    float sx = 0.f, sy = 0.f;
#pragma unroll
    for (int sp = 0; sp < NSPLIT; sp++) {
        float2 v = base[(size_t)sp << 13];
        sx += v.x; sy += v.y;
    }
    const uint32_t hi = pack2h(sx, sy);
    const uint32_t lane = (uint32_t)(j & 7) * 4 + (d2 & 3);
    const uint32_t comp = (uint32_t)(d2 >> 2) & 1;            // b0 / b1
    const uint32_t slot = (((uint32_t)(b * 16 + (j >> 3)) * 8 + (d2 >> 3)) * 32 + lane);
    ((uint32_t*)g_frag)[slot * 2 + comp] = hi;
}

// ---------------------------------------------------------------------------
// Kernel 3 (R9 skeleton): O_tile(64x128) = Qhi_tile @ Ghi.  Q hi plane in
// smem; G fragments (uint2) LDG.64 from gmem (L2-hot), 2-deep prefetch.
// ---------------------------------------------------------------------------
__global__ __launch_bounds__(256, 3) void qg_hmma(const float* __restrict__ dec,
                                                  float* __restrict__ out) {
    extern __shared__ char smem[];
    const uint32_t sb = smem_u32(smem);
    const int tid = threadIdx.x, wid = tid >> 5, lid = tid & 31;
    const int b = blockIdx.y, qt = blockIdx.x;

    const float4* qsrc = (const float4*)(dec + ((size_t)(b * 32 + qt) << 13));
    float4 q[8];
#pragma unroll
    for (int v = 0; v < 8; v++) q[v] = qsrc[tid + v * 256];
#pragma unroll
    for (int v = 0; v < 8; v++) {
        int idx = tid + v * 256;
        int row = idx >> 5, d4 = idx & 31;
        uint32_t off = (uint32_t)row * RSTRIDE + (uint32_t)d4 * 8;
        *(uint2*)(smem + off) =
            make_uint2(pack2h(q[v].x, q[v].y), pack2h(q[v].z, q[v].w));
    }
    __syncthreads();

    const int wm = (wid >> 2) * 32, wn = (wid & 3) * 32;
    const uint2* gf = g_frag + ((size_t)(b * 16 + (wn >> 3)) * 8) * 32 + lid;

    float acc[2][4][4];
#pragma unroll
    for (int mi = 0; mi < 2; mi++)
#pragma unroll
        for (int nj = 0; nj < 4; nj++)
#pragma unroll
            for (int r = 0; r < 4; r++) acc[mi][nj][r] = 0.0f;

    const uint32_t aRow = lid & 15;
    const uint32_t aCol = (lid >> 4) << 3;

    uint2 Gb[2][4];
#pragma unroll
    for (int nj = 0; nj < 4; nj++) Gb[0][nj] = gf[nj * 256];
#pragma unroll
    for (int nj = 0; nj < 4; nj++) Gb[1][nj] = gf[nj * 256 + 32];

#pragma unroll
    for (int kk = 0; kk < 8; kk++) {
        const int k0 = kk * 16;
        const int buf = kk & 1;
        uint32_t Ah[2][4];
#pragma unroll
        for (int mi = 0; mi < 2; mi++) {
            uint32_t off = (uint32_t)(wm + mi * 16 + aRow) * RSTRIDE +
                           (uint32_t)(k0 + aCol) * 2;
            ldsm_x4(Ah[mi], sb + off);
        }
#pragma unroll
        for (int mi = 0; mi < 2; mi++)
#pragma unroll
            for (int nj = 0; nj < 4; nj++)
                mma16816(acc[mi][nj], Ah[mi], Gb[buf][nj].x, Gb[buf][nj].y);
        if (kk < 6) {
#pragma unroll
            for (int nj = 0; nj < 4; nj++)
                Gb[buf][nj] = gf[nj * 256 + (kk + 2) * 32];
        }
    }

    float* outp = out + ((size_t)(b * 32 + qt) << 13);
    warp_epilogue32(outp, wm, wn, lid, acc);
}

// ---------------------------------------------------------------------------
// Launch
// ---------------------------------------------------------------------------
extern "C" void kernel_launch(void* const* d_in, const int* in_sizes, int n_in,
                              void* d_out, int out_size) {
    const float* enc = (const float*)d_in[0];
    const float* dec = (const float*)d_in[1];
    float* out = (float*)d_out;

    cudaFuncSetAttribute(ete_hmma, cudaFuncAttributeMaxDynamicSharedMemorySize,
                         2 * STAGE_SZ);
    cudaFuncSetAttribute(qg_hmma, cudaFuncAttributeMaxDynamicSharedMemorySize,
                         PLANE_T);

    ete_hmma<<<dim3(2 * NSPLIT, BB), 256, 2 * STAGE_SZ>>>(enc);
    reduce_g<<<256, 256>>>();
    qg_hmma<<<dim3(32, BB), 256, PLANE_T>>>(dec, out);
}

// round 15
// speedup vs baseline: 1.2959x; 1.1015x over previous
#include <cuda_runtime.h>
#include <cuda_fp16.h>
#include <cstdint>

// LuongAttention: O[b] = (Q Eᵀ) E == Q (EᵀE).  G = EᵀE per batch (128x128).
// R15: R14 (single-term fp16 HMMA in both GEMMs, err ~3e-4) + fp16 partials:
// ete stores partial G tiles as half2 (C-layout, L1-bypass), reduce reads
// half2 and accumulates fp32.  Halves the partial round-trip (8W+8R -> 4+4).
// Error model: +~2.4e-4 -> total ~4.5e-4 vs 1e-3 tolerance.

#define BB 8
#define NSPLIT 16
#define RSTRIDE 272                 // plane row stride, bytes
#define PLANE_T (64 * RSTRIDE)      // 17408 B (hi plane, 64 tokens)
#define STAGE_SZ PLANE_T            // one (hi-only) plane per stage

// fp16 partials: [b][sp][row 128][d2 64] half2 words.
__device__ uint32_t g_parth[BB * NSPLIT * 128 * 64];   // 4 MB
// B-fragment layout: [b][n8tile 16][kstep 8][lane 32] = uint2 {hi_b0, hi_b1}.
__device__ uint2 g_frag[BB * 16 * 8 * 32];             // 256 KB

// ---------------- helpers ----------------
__device__ __forceinline__ uint32_t smem_u32(const void* p) {
    uint32_t a;
    asm("{ .reg .u64 t; cvta.to.shared.u64 t, %1; cvt.u32.u64 %0, t; }"
        : "=r"(a) : "l"(p));
    return a;
}
__device__ __forceinline__ void ldsm_x4(uint32_t (&r)[4], uint32_t addr) {
    asm volatile("ldmatrix.sync.aligned.m8n8.x4.shared.b16 {%0,%1,%2,%3}, [%4];"
                 : "=r"(r[0]), "=r"(r[1]), "=r"(r[2]), "=r"(r[3]) : "r"(addr));
}
__device__ __forceinline__ void ldsm_x4_t(uint32_t (&r)[4], uint32_t addr) {
    asm volatile("ldmatrix.sync.aligned.m8n8.x4.trans.shared.b16 {%0,%1,%2,%3}, [%4];"
                 : "=r"(r[0]), "=r"(r[1]), "=r"(r[2]), "=r"(r[3]) : "r"(addr));
}
__device__ __forceinline__ void mma16816(float (&d)[4], const uint32_t (&a)[4],
                                         uint32_t b0, uint32_t b1) {
    asm volatile(
        "mma.sync.aligned.m16n8k16.row.col.f32.f16.f16.f32 "
        "{%0,%1,%2,%3}, {%4,%5,%6,%7}, {%8,%9}, {%0,%1,%2,%3};"
        : "+f"(d[0]), "+f"(d[1]), "+f"(d[2]), "+f"(d[3])
        : "r"(a[0]), "r"(a[1]), "r"(a[2]), "r"(a[3]), "r"(b0), "r"(b1));
}
__device__ __forceinline__ uint32_t pack2h(float f0, float f1) {
    __half2 h = __floats2half2_rn(f0, f1);
    return *(uint32_t*)&h;
}

// Convert+store one 64-token register batch into a stage's hi plane.
__device__ __forceinline__ void stage_store(char* smem, int stage, int tid,
                                            const float4* q) {
    char* base = smem + stage * STAGE_SZ;
#pragma unroll
    for (int v = 0; v < 8; v++) {
        int idx = tid + v * 256;
        int t = idx >> 5, d4 = idx & 31;
        uint32_t off = (uint32_t)t * RSTRIDE + (uint32_t)d4 * 8;
        *(uint2*)(base + off) =
            make_uint2(pack2h(q[v].x, q[v].y), pack2h(q[v].z, q[v].w));
    }
}

// MMA over one 64-token stage (4 ksteps), trans layout, 32x32 warp tile,
// single term (hi·hi).
__device__ __forceinline__ void stage_mma(uint32_t sbase, int wm, int wn, int lid,
                                          float (&acc)[2][4][4]) {
    const uint32_t aRow = (lid & 7) + ((lid >> 4) << 3);
    const uint32_t aCol = ((lid >> 3) & 1) << 3;
    const uint32_t bRow = (lid & 7) + (((lid >> 3) & 1) << 3);
    const uint32_t bCol = (lid >> 4) << 3;

#pragma unroll
    for (int kk = 0; kk < 4; kk++) {
        const int k0 = kk * 16;
        uint32_t Ah[2][4], Bh[2][4];
#pragma unroll
        for (int mi = 0; mi < 2; mi++) {
            uint32_t off = (uint32_t)(k0 + aRow) * RSTRIDE +
                           (uint32_t)(wm + mi * 16 + aCol) * 2;
            ldsm_x4_t(Ah[mi], sbase + off);
        }
#pragma unroll
        for (int np = 0; np < 2; np++) {
            uint32_t off = (uint32_t)(k0 + bRow) * RSTRIDE +
                           (uint32_t)(wn + np * 16 + bCol) * 2;
            ldsm_x4_t(Bh[np], sbase + off);
        }
#pragma unroll
        for (int mi = 0; mi < 2; mi++)
#pragma unroll
            for (int nj = 0; nj < 4; nj++) {
                const int np = nj >> 1, pr = (nj & 1) << 1;
                mma16816(acc[mi][nj], Ah[mi], Bh[np][pr], Bh[np][pr + 1]);
            }
    }
}

// ---------------------------------------------------------------------------
// Kernel 1: partial EᵀE.  CTA (sp, half): K = 128 tokens in two 64-token
// stages, double-buffered; stage-1 LDG overlaps stage-0 MMA.
// Epilogue: fp16 half2 partial tile, L1-bypass stores.
// Grid (2*NSPLIT, BB); bx = sp*2 + half.
// ---------------------------------------------------------------------------
__global__ __launch_bounds__(256) void ete_hmma(const float* __restrict__ enc) {
    extern __shared__ char smem[];
    const uint32_t sb = smem_u32(smem);
    const int tid = threadIdx.x, wid = tid >> 5, lid = tid & 31;
    const int sp = blockIdx.x >> 1, half = blockIdx.x & 1, b = blockIdx.y;

    const float4* src =
        (const float4*)(enc + (size_t)(b * NSPLIT + sp) * (128 * 128));

    float4 q0[8];
#pragma unroll
    for (int v = 0; v < 8; v++) q0[v] = src[tid + v * 256];
    stage_store(smem, 0, tid, q0);
    __syncthreads();

    // Stage 1 loads issued NOW — they fly while stage-0 MMAs run.
    float4 q1[8];
#pragma unroll
    for (int v = 0; v < 8; v++) q1[v] = src[2048 + tid + v * 256];

    const int wm = half * 64 + (wid >> 2) * 32, wn = (wid & 3) * 32;
    float acc[2][4][4];
#pragma unroll
    for (int mi = 0; mi < 2; mi++)
#pragma unroll
        for (int nj = 0; nj < 4; nj++)
#pragma unroll
            for (int r = 0; r < 4; r++) acc[mi][nj][r] = 0.0f;

    stage_mma(sb, wm, wn, lid, acc);            // tokens 0..63

    stage_store(smem, 1, tid, q1);
    __syncthreads();

    stage_mma(sb + STAGE_SZ, wm, wn, lid, acc); // tokens 64..127

    // Epilogue: fp16 half2 partial tile (C layout), bypassing L1.
    uint32_t* outp = g_parth + (((size_t)(b * NSPLIT + sp)) << 13);
    const int g = lid >> 2, tig = lid & 3;
#pragma unroll
    for (int mi = 0; mi < 2; mi++)
#pragma unroll
        for (int nj = 0; nj < 4; nj++) {
            const int row = wm + mi * 16 + g;
            const int d2 = (wn + nj * 8 + 2 * tig) >> 1;
            __stcg(outp + row * 64 + d2, pack2h(acc[mi][nj][0], acc[mi][nj][1]));
            __stcg(outp + (row + 8) * 64 + d2, pack2h(acc[mi][nj][2], acc[mi][nj][3]));
        }
}

// ---------------------------------------------------------------------------
// Kernel 2: reduce 16 fp16 partials (fp32 accum); emit G rows as fp16
// hi-only B-fragments.
// ---------------------------------------------------------------------------
__global__ __launch_bounds__(256) void reduce_g() {
    const int e2 = blockIdx.x * 256 + threadIdx.x;  // 0..65535
    const int b = e2 >> 13;
    const int r = e2 & 8191;
    const int j = r >> 6, d2 = r & 63;
    const uint32_t* base = g_parth + (((size_t)b * NSPLIT) << 13) + j * 64 + d2;
    float sx = 0.f, sy = 0.f;
#pragma unroll
    for (int sp = 0; sp < NSPLIT; sp++) {
        uint32_t u = __ldcg(base + ((size_t)sp << 13));
        float2 v = __half22float2(*(__half2*)&u);
        sx += v.x; sy += v.y;
    }
    const uint32_t hi = pack2h(sx, sy);
    const uint32_t lane = (uint32_t)(j & 7) * 4 + (d2 & 3);
    const uint32_t comp = (uint32_t)(d2 >> 2) & 1;            // b0 / b1
    const uint32_t slot = (((uint32_t)(b * 16 + (j >> 3)) * 8 + (d2 >> 3)) * 32 + lane);
    ((uint32_t*)g_frag)[slot * 2 + comp] = hi;
}

// ---------------------------------------------------------------------------
// Kernel 3 (R14/R9 skeleton): O_tile(64x128) = Qhi_tile @ Ghi.  Q hi plane
// in smem; G fragments (uint2) LDG.64 from gmem (L2-hot), 2-deep prefetch.
// ---------------------------------------------------------------------------
__global__ __launch_bounds__(256, 3) void qg_hmma(const float* __restrict__ dec,
                                                  float* __restrict__ out) {
    extern __shared__ char smem[];
    const uint32_t sb = smem_u32(smem);
    const int tid = threadIdx.x, wid = tid >> 5, lid = tid & 31;
    const int b = blockIdx.y, qt = blockIdx.x;

    const float4* qsrc = (const float4*)(dec + ((size_t)(b * 32 + qt) << 13));
    float4 q[8];
#pragma unroll
    for (int v = 0; v < 8; v++) q[v] = qsrc[tid + v * 256];
#pragma unroll
    for (int v = 0; v < 8; v++) {
        int idx = tid + v * 256;
        int row = idx >> 5, d4 = idx & 31;
        uint32_t off = (uint32_t)row * RSTRIDE + (uint32_t)d4 * 8;
        *(uint2*)(smem + off) =
            make_uint2(pack2h(q[v].x, q[v].y), pack2h(q[v].z, q[v].w));
    }
    __syncthreads();

    const int wm = (wid >> 2) * 32, wn = (wid & 3) * 32;
    const uint2* gf = g_frag + ((size_t)(b * 16 + (wn >> 3)) * 8) * 32 + lid;

    float acc[2][4][4];
#pragma unroll
    for (int mi = 0; mi < 2; mi++)
#pragma unroll
        for (int nj = 0; nj < 4; nj++)
#pragma unroll
            for (int r = 0; r < 4; r++) acc[mi][nj][r] = 0.0f;

    const uint32_t aRow = lid & 15;
    const uint32_t aCol = (lid >> 4) << 3;

    uint2 Gb[2][4];
#pragma unroll
    for (int nj = 0; nj < 4; nj++) Gb[0][nj] = gf[nj * 256];
#pragma unroll
    for (int nj = 0; nj < 4; nj++) Gb[1][nj] = gf[nj * 256 + 32];

#pragma unroll
    for (int kk = 0; kk < 8; kk++) {
        const int k0 = kk * 16;
        const int buf = kk & 1;
        uint32_t Ah[2][4];
#pragma unroll
        for (int mi = 0; mi < 2; mi++) {
            uint32_t off = (uint32_t)(wm + mi * 16 + aRow) * RSTRIDE +
                           (uint32_t)(k0 + aCol) * 2;
            ldsm_x4(Ah[mi], sb + off);
        }
#pragma unroll
        for (int mi = 0; mi < 2; mi++)
#pragma unroll
            for (int nj = 0; nj < 4; nj++)
                mma16816(acc[mi][nj], Ah[mi], Gb[buf][nj].x, Gb[buf][nj].y);
        if (kk < 6) {
#pragma unroll
            for (int nj = 0; nj < 4; nj++)
                Gb[buf][nj] = gf[nj * 256 + (kk + 2) * 32];
        }
    }

    float* outp = out + ((size_t)(b * 32 + qt) << 13);
    const int g = lid >> 2, tig = lid & 3;
#pragma unroll
    for (int mi = 0; mi < 2; mi++)
#pragma unroll
        for (int nj = 0; nj < 4; nj++) {
            const int row = wm + mi * 16 + g;
            const int col = wn + nj * 8 + 2 * tig;
            *(float2*)(outp + row * 128 + col) =
                make_float2(acc[mi][nj][0], acc[mi][nj][1]);
            *(float2*)(outp + (row + 8) * 128 + col) =
                make_float2(acc[mi][nj][2], acc[mi][nj][3]);
        }
}

// ---------------------------------------------------------------------------
// Launch
// ---------------------------------------------------------------------------
extern "C" void kernel_launch(void* const* d_in, const int* in_sizes, int n_in,
                              void* d_out, int out_size) {
    const float* enc = (const float*)d_in[0];
    const float* dec = (const float*)d_in[1];
    float* out = (float*)d_out;

    cudaFuncSetAttribute(ete_hmma, cudaFuncAttributeMaxDynamicSharedMemorySize,
                         2 * STAGE_SZ);
    cudaFuncSetAttribute(qg_hmma, cudaFuncAttributeMaxDynamicSharedMemorySize,
                         PLANE_T);

    ete_hmma<<<dim3(2 * NSPLIT, BB), 256, 2 * STAGE_SZ>>>(enc);
    reduce_g<<<256, 256>>>();
    qg_hmma<<<dim3(32, BB), 256, PLANE_T>>>(dec, out);
}